// round 15
// baseline (speedup 1.0000x reference)
#include <cuda_runtime.h>
#include <math.h>

#define DD   128
#define HH   8
#define EDIM 16
#define NMAX 50000
#define EMAX 800000
#define DEGPAD 51200
#define FULLMASK 0xffffffffu

typedef unsigned long long ull;
union F2U { ull u; float2 f; };

__device__ __forceinline__ void fma2(ull &d, ull a, ull b) {
    asm("fma.rn.f32x2 %0, %1, %2, %0;" : "+l"(d) : "l"(a), "l"(b));
}

// ---------------- scratch ----------------
__device__ float g_xl[NMAX * DD];
__device__ float g_xr[NMAX * DD];
__device__ float g_Wp[64 * 512];
__device__ int   g_deg[DEGPAD];
__device__ int   g_off[NMAX + 1];
__device__ int   g_woff[NMAX + 1];
__device__ int2  g_pep[EMAX];         // CSR-ordered (edge id, src id)
__device__ int   g_bsum[64];
__device__ int   g_bpre[64];
__device__ float g_sum[DD];
__device__ float g_sumsq[DD];

// ---------------- merged init: zero + packW ----------------
__global__ void k_init(const float* __restrict__ Wl, const float* __restrict__ Wr) {
    int i = blockIdx.x * blockDim.x + threadIdx.x;
    int stride = gridDim.x * blockDim.x;
    if (i < 64 * 512) {
        int q  = i & 3;
        int tc = (i >> 2) & 31;
        int f  = (i >> 7) & 3;
        int kp = i >> 9;
        int m = f >> 1;
        int ci = ((f & 1) << 1) | (q >> 1);
        int ki = q & 1;
        g_Wp[i] = (m ? Wr : Wl)[(kp * 2 + ki) * DD + tc * 4 + ci];
    }
    for (int j = i; j < DEGPAD; j += stride) g_deg[j] = 0;
    if (i < DD) { g_sum[i] = 0.f; g_sumsq[i] = 0.f; }
}

// ---------------- CSR hist ----------------
__global__ void k_hist(const int* __restrict__ ei, int E) {
    int e = blockIdx.x * blockDim.x + threadIdx.x;
    if (e < E) atomicAdd(&g_deg[ei[E + e]], 1);
}

// ---------------- node transform: warp-split, 8 rows/warp, 32-row tile -------
__global__ __launch_bounds__(256, 2) void k_node(
    const int* __restrict__ x, const float* __restrict__ emb,
    const float* __restrict__ bl, const float* __restrict__ br, int n)
{
    __shared__ float hs[2][32 * DD];   // 32 KB ping-pong
    int tid = threadIdx.x;
    int tc = tid & 31;
    int g  = tid >> 5;
    int mat = g & 1;
    int tr  = g >> 1;
    float4 bv = ((const float4*)(mat ? br : bl))[tc];
    float* gout = mat ? g_xr : g_xl;
    const float SQ = 11.313708498984761f;
    int ntiles = (n + 31) >> 5;

    int t = blockIdx.x;
    if (t >= ntiles) return;
    int cur = 0;

    {
        int base = t * 32;
        int nrows = min(32, n - base);
        for (int i = tid; i < 32 * 32; i += 256) {
            int r = i >> 5, c4 = i & 31;
            float4 v = make_float4(0.f, 0.f, 0.f, 0.f);
            if (r < nrows) {
                const float4* src = (const float4*)(emb + (size_t)x[base + r] * DD);
                v = src[c4];
                v.x *= SQ; v.y *= SQ; v.z *= SQ; v.w *= SQ;
            }
            ((float4*)hs[cur])[i] = v;
        }
    }
    __syncthreads();

    while (t < ntiles) {
        int tn = t + gridDim.x;
        if (tn < ntiles) {
            int base = tn * 32;
            int nrows = min(32, n - base);
            for (int i = tid; i < 32 * 32; i += 256) {
                int r = i >> 5, c4 = i & 31;
                float4 v = make_float4(0.f, 0.f, 0.f, 0.f);
                if (r < nrows) {
                    const float4* src = (const float4*)(emb + (size_t)x[base + r] * DD);
                    v = src[c4];
                    v.x *= SQ; v.y *= SQ; v.z *= SQ; v.w *= SQ;
                }
                ((float4*)hs[cur ^ 1])[i] = v;
            }
        }

        ull acc[8][4];
        #pragma unroll
        for (int r = 0; r < 8; r++)
            #pragma unroll
            for (int c = 0; c < 4; c++) acc[r][c] = 0ull;

        const float* hbase = hs[cur] + tr * 8 * DD;
        const float* wbase = g_Wp + mat * 256 + tc * 4;
        #pragma unroll 2
        for (int kp = 0; kp < 64; kp++) {
            ulonglong2 L0 = *(const ulonglong2*)(wbase + kp * 512);
            ulonglong2 L1 = *(const ulonglong2*)(wbase + kp * 512 + 128);
            ull w[4] = { L0.x, L0.y, L1.x, L1.y };
            #pragma unroll
            for (int r = 0; r < 8; r++) {
                ull hp = *(const ull*)(hbase + r * DD + 2 * kp);
                #pragma unroll
                for (int c = 0; c < 4; c++)
                    fma2(acc[r][c], hp, w[c]);
            }
        }

        int base = t * 32;
        #pragma unroll
        for (int r = 0; r < 8; r++) {
            int row = base + tr * 8 + r;
            if (row < n) {
                F2U t0, t1, t2, t3;
                t0.u = acc[r][0]; t1.u = acc[r][1];
                t2.u = acc[r][2]; t3.u = acc[r][3];
                float4 o = make_float4(t0.f.x + t0.f.y + bv.x, t1.f.x + t1.f.y + bv.y,
                                       t2.f.x + t2.f.y + bv.z, t3.f.x + t3.f.y + bv.w);
                *(float4*)(gout + (size_t)row * DD + tc * 4) = o;
            }
        }
        __syncthreads();
        cur ^= 1;
        t = tn;
    }
}

// ---------------- CSR scan ----------------
__global__ __launch_bounds__(256) void k_bsum() {
    __shared__ int ws[8];
    int b = blockIdx.x, tid = threadIdx.x;
    int4 d = ((const int4*)g_deg)[b * 256 + tid];
    int s = d.x + d.y + d.z + d.w;
    #pragma unroll
    for (int o = 16; o > 0; o >>= 1) s += __shfl_xor_sync(FULLMASK, s, o);
    if ((tid & 31) == 0) ws[tid >> 5] = s;
    __syncthreads();
    if (tid == 0) {
        int t = 0;
        #pragma unroll
        for (int i = 0; i < 8; i++) t += ws[i];
        g_bsum[b] = t;
    }
}

__global__ void k_bscan(int nb) {
    __shared__ int ws[2];
    int t = threadIdx.x;
    int lane = t & 31, w = t >> 5;
    int v = (t < nb) ? g_bsum[t] : 0;
    int s = v;
    #pragma unroll
    for (int o = 1; o < 32; o <<= 1) {
        int u = __shfl_up_sync(FULLMASK, s, o);
        if (lane >= o) s += u;
    }
    if (lane == 31) ws[w] = s;
    __syncthreads();
    int add = (w == 1) ? ws[0] : 0;
    g_bpre[t] = s - v + add;
}

__global__ __launch_bounds__(256) void k_off(int n) {
    __shared__ int wtot[8], wpre[8];
    int b = blockIdx.x, tid = threadIdx.x;
    int lane = tid & 31, w = tid >> 5;
    int4 d = ((const int4*)g_deg)[b * 256 + tid];
    int s0 = d.x, s01 = s0 + d.y, s012 = s01 + d.z;
    int tsum = s012 + d.w;
    int inc = tsum;
    #pragma unroll
    for (int o = 1; o < 32; o <<= 1) {
        int u = __shfl_up_sync(FULLMASK, inc, o);
        if (lane >= o) inc += u;
    }
    if (lane == 31) wtot[w] = inc;
    __syncthreads();
    if (w == 0 && lane < 8) {
        int v = wtot[lane];
        int s = v;
        #pragma unroll
        for (int o = 1; o < 8; o <<= 1) {
            int u = __shfl_up_sync(0xffu, s, o);
            if (lane >= o) s += u;
        }
        wpre[lane] = s - v;
    }
    __syncthreads();
    int excl = inc - tsum + wpre[w] + g_bpre[b];
    int idx = b * 1024 + tid * 4;
    if (idx     <= n) { g_off[idx]     = excl;        g_woff[idx]     = excl; }
    if (idx + 1 <= n) { g_off[idx + 1] = excl + s0;   g_woff[idx + 1] = excl + s0; }
    if (idx + 2 <= n) { g_off[idx + 2] = excl + s01;  g_woff[idx + 2] = excl + s01; }
    if (idx + 3 <= n) { g_off[idx + 3] = excl + s012; g_woff[idx + 3] = excl + s012; }
}

// scatter: single int2 (edge id, src id) per slot — one 8B sector write
__global__ void k_scatter(const int* __restrict__ ei, int E) {
    int e = blockIdx.x * blockDim.x + threadIdx.x;
    if (e < E) {
        int dst = ei[E + e];
        int pos = atomicAdd(&g_woff[dst], 1);
        g_pep[pos] = make_int2(e, ei[e]);
    }
}

// ---------------- fused score + softmax + aggregation + BN stats -------------
// leaky folded into att: s += (m>0 ? a : 0.2a)*m  (select on ALU pipe)
__device__ __forceinline__ void edge_compute(
    const float* eew, float4 xlv, float4 xrv, float4 a4, float4 a02,
    const ull (&wreg)[8][4], float4 &acc, float &ds)
{
    ull p0 = 0, p1 = 0, p2 = 0, p3 = 0;
    #pragma unroll
    for (int dp = 0; dp < 8; dp++) {
        ull a = *(const ull*)(eew + 2 * dp);   // smem broadcast
        fma2(p0, a, wreg[dp][0]);
        fma2(p1, a, wreg[dp][1]);
        fma2(p2, a, wreg[dp][2]);
        fma2(p3, a, wreg[dp][3]);
    }
    F2U u0, u1, u2, u3;
    u0.u = p0; u1.u = p1; u2.u = p2; u3.u = p3;
    float mx = xlv.x + xrv.x + u0.f.x + u0.f.y;
    float my = xlv.y + xrv.y + u1.f.x + u1.f.y;
    float mz = xlv.z + xrv.z + u2.f.x + u2.f.y;
    float mw = xlv.w + xrv.w + u3.f.x + u3.f.y;
    float cx = mx > 0.f ? a4.x : a02.x;
    float cy = my > 0.f ? a4.y : a02.y;
    float cz = mz > 0.f ? a4.z : a02.z;
    float cw = mw > 0.f ? a4.w : a02.w;
    float s = cx * mx;
    s = fmaf(cy, my, s);
    s = fmaf(cz, mz, s);
    s = fmaf(cw, mw, s);
    s += __shfl_xor_sync(FULLMASK, s, 1);
    s += __shfl_xor_sync(FULLMASK, s, 2);
    float w = __expf(s);
    ds += w;
    acc.x = fmaf(w, xlv.x, acc.x);
    acc.y = fmaf(w, xlv.y, acc.y);
    acc.z = fmaf(w, xlv.z, acc.z);
    acc.w = fmaf(w, xlv.w, acc.w);
}

#define EDGE_STAGE(Q)                                                          \
    {                                                                          \
        const float* ep = sew + j * EDIM;                                      \
        float4 xlv = Q;                                                        \
        if (j + 4 < m) {                                                       \
            int s4i = __shfl_sync(FULLMASK, sL, j + 4);                        \
            Q = *(const float4*)(g_xl + (size_t)s4i * DD + col);               \
        }                                                                      \
        edge_compute(ep, xlv, xrv, a4, a02, wreg, acc, ds);                    \
        j++;                                                                   \
    }

__global__ __launch_bounds__(128, 4) void k_fused(
    const float* __restrict__ ew,
    const float* __restrict__ We, const float* __restrict__ att,
    const float* __restrict__ bias, float* __restrict__ out, int n)
{
    __shared__ float sew_all[4][32 * EDIM];   // 8 KB
    __shared__ float ssum[4][DD], ssq[4][DD]; // 4 KB
    int lane = threadIdx.x & 31;
    int wid  = threadIdx.x >> 5;
    float* sew = sew_all[wid];
    int gw = blockIdx.x * 4 + wid;
    int nw = gridDim.x * 4;
    int col = lane * 4;

    ull wreg[8][4];
    #pragma unroll
    for (int dp = 0; dp < 8; dp++) {
        #pragma unroll
        for (int c = 0; c < 4; c++) {
            F2U t;
            t.f.x = __ldg(We + (2 * dp)     * DD + col + c);
            t.f.y = __ldg(We + (2 * dp + 1) * DD + col + c);
            wreg[dp][c] = t.u;
        }
    }
    float4 a4 = ((const float4*)att)[lane];
    float4 a02 = make_float4(0.2f * a4.x, 0.2f * a4.y, 0.2f * a4.z, 0.2f * a4.w);
    float4 b4 = ((const float4*)bias)[lane];
    float4 sacc = make_float4(0.f, 0.f, 0.f, 0.f);
    float4 qacc = make_float4(0.f, 0.f, 0.f, 0.f);

    for (int v = gw; v < n; v += nw) {
        int start = g_off[v];
        int end   = g_off[v + 1];
        float4 xrv = *(const float4*)(g_xr + (size_t)v * DD + col);
        float4 acc = make_float4(0.f, 0.f, 0.f, 0.f);
        float ds = 0.f;

        for (int c0 = start; c0 < end; c0 += 32) {
            int m = min(32, end - c0);
            int sL = 0;
            if (lane < m) {
                int2 pe = g_pep[c0 + lane];        // one coalesced 8B load
                sL = pe.y;
                const float4* src = (const float4*)(ew + (size_t)pe.x * EDIM);
                float4* dst = (float4*)(sew + lane * EDIM);
                dst[0] = src[0]; dst[1] = src[1]; dst[2] = src[2]; dst[3] = src[3];
            }
            __syncwarp();

            int s0 = __shfl_sync(FULLMASK, sL, 0);
            int s1 = __shfl_sync(FULLMASK, sL, 1);
            int s2 = __shfl_sync(FULLMASK, sL, 2);
            int s3 = __shfl_sync(FULLMASK, sL, 3);
            float4 xq0 = *(const float4*)(g_xl + (size_t)s0 * DD + col);
            float4 xq1 = *(const float4*)(g_xl + (size_t)s1 * DD + col);
            float4 xq2 = *(const float4*)(g_xl + (size_t)s2 * DD + col);
            float4 xq3 = *(const float4*)(g_xl + (size_t)s3 * DD + col);

            int j = 0;
            while (j < m) {
                EDGE_STAGE(xq0)
                if (j >= m) break;
                EDGE_STAGE(xq1)
                if (j >= m) break;
                EDGE_STAGE(xq2)
                if (j >= m) break;
                EDGE_STAGE(xq3)
            }
            __syncwarp();
        }
        float invd = (end > start) ? 1.f / ds : 0.f;
        float4 o = make_float4(fmaf(acc.x, invd, b4.x), fmaf(acc.y, invd, b4.y),
                               fmaf(acc.z, invd, b4.z), fmaf(acc.w, invd, b4.w));
        *(float4*)(out + (size_t)v * DD + col) = o;
        sacc.x += o.x; sacc.y += o.y; sacc.z += o.z; sacc.w += o.w;
        qacc.x = fmaf(o.x, o.x, qacc.x);
        qacc.y = fmaf(o.y, o.y, qacc.y);
        qacc.z = fmaf(o.z, o.z, qacc.z);
        qacc.w = fmaf(o.w, o.w, qacc.w);
    }

    *(float4*)&ssum[wid][col] = sacc;
    *(float4*)&ssq[wid][col]  = qacc;
    __syncthreads();
    int ch = threadIdx.x;
    float s = ssum[0][ch] + ssum[1][ch] + ssum[2][ch] + ssum[3][ch];
    float q = ssq[0][ch]  + ssq[1][ch]  + ssq[2][ch]  + ssq[3][ch];
    atomicAdd(&g_sum[ch], s);
    atomicAdd(&g_sumsq[ch], q);
}

// ---------------- BN finalize folded into apply ----------------
__global__ __launch_bounds__(256) void k_apply(
    const float* __restrict__ gamma, const float* __restrict__ beta,
    float* __restrict__ out, int n)
{
    __shared__ float ssc[DD], ssh[DD];
    int t = threadIdx.x;
    if (t < DD) {
        float invn = 1.f / (float)n;
        float mean = g_sum[t] * invn;
        float var  = g_sumsq[t] * invn - mean * mean;
        if (var < 0.f) var = 0.f;
        float inv = rsqrtf(var + 1e-5f);
        float sc = gamma[t] * inv;
        ssc[t] = sc;
        ssh[t] = beta[t] - mean * sc;
    }
    __syncthreads();
    int i = blockIdx.x * blockDim.x + t;
    int total = n * (DD / 4);
    if (i < total) {
        float4 v = ((float4*)out)[i];
        float4 sc = ((float4*)ssc)[i & 31];
        float4 sh = ((float4*)ssh)[i & 31];
        float yx = fmaf(v.x, sc.x, sh.x);
        float yy = fmaf(v.y, sc.y, sh.y);
        float yz = fmaf(v.z, sc.z, sh.z);
        float yw = fmaf(v.w, sc.w, sh.w);
        v.x = yx > 0.f ? yx : 0.01f * yx;
        v.y = yy > 0.f ? yy : 0.01f * yy;
        v.z = yz > 0.f ? yz : 0.01f * yz;
        v.w = yw > 0.f ? yw : 0.01f * yw;
        ((float4*)out)[i] = v;
    }
}

// ---------------- launch ----------------
extern "C" void kernel_launch(void* const* d_in, const int* in_sizes, int n_in,
                              void* d_out, int out_size)
{
    const int*   x     = (const int*)  d_in[0];
    const int*   ei    = (const int*)  d_in[1];
    const float* ew    = (const float*)d_in[2];
    const float* emb   = (const float*)d_in[3];
    const float* Wl    = (const float*)d_in[4];
    const float* bl    = (const float*)d_in[5];
    const float* Wr    = (const float*)d_in[6];
    const float* br    = (const float*)d_in[7];
    const float* att   = (const float*)d_in[8];
    const float* We    = (const float*)d_in[9];
    const float* bias  = (const float*)d_in[10];
    const float* gamma = (const float*)d_in[11];
    const float* beta  = (const float*)d_in[12];
    float* out = (float*)d_out;

    int n = in_sizes[0];
    int E = in_sizes[1] / 2;
    int nb = (n + 1023) / 1024;

    k_init<<<200, 256>>>(Wl, Wr);
    k_hist<<<(E + 255) / 256, 256>>>(ei, E);
    k_bsum<<<nb, 256>>>();
    k_node<<<296, 256>>>(x, emb, bl, br, n);   // 4th launch -> ncu capture
    k_bscan<<<1, 64>>>(nb);
    k_off<<<nb, 256>>>(n);
    k_scatter<<<(E + 255) / 256, 256>>>(ei, E);

    k_fused<<<592, 128>>>(ew, We, att, bias, out, n);

    k_apply<<<(n * (DD / 4) + 255) / 256, 256>>>(gamma, beta, out, n);
}

// round 16
// speedup vs baseline: 1.0796x; 1.0796x over previous
#include <cuda_runtime.h>
#include <math.h>

#define DD   128
#define HH   8
#define EDIM 16
#define NMAX 50000
#define EMAX 800000
#define DEGPAD 51200
#define FULLMASK 0xffffffffu

typedef unsigned long long ull;
union F2U { ull u; float2 f; };

__device__ __forceinline__ void fma2(ull &d, ull a, ull b) {
    asm("fma.rn.f32x2 %0, %1, %2, %0;" : "+l"(d) : "l"(a), "l"(b));
}

// ---------------- scratch ----------------
__device__ float g_xl[NMAX * DD];
__device__ float g_xr[NMAX * DD];
__device__ float g_Wp[64 * 512];
__device__ int   g_deg[DEGPAD];          // static zero-init; re-zeroed by k_scan
__device__ int   g_off[NMAX + 1];
__device__ int   g_woff[NMAX + 1];
__device__ int   g_perm[EMAX];
__device__ ull   g_scanstate[64];        // lookback state; zeroed by k_pre
__device__ float g_sum[DD];
__device__ float g_sumsq[DD];

// ---------------- launch 1: packW + hist + zero small state ----------------
__global__ void k_pre(const float* __restrict__ Wl, const float* __restrict__ Wr,
                      const int* __restrict__ ei, int E)
{
    int i = blockIdx.x * blockDim.x + threadIdx.x;
    if (i < 64 * 512) {
        int q  = i & 3;
        int tc = (i >> 2) & 31;
        int f  = (i >> 7) & 3;
        int kp = i >> 9;
        int m = f >> 1;
        int ci = ((f & 1) << 1) | (q >> 1);
        int ki = q & 1;
        g_Wp[i] = (m ? Wr : Wl)[(kp * 2 + ki) * DD + tc * 4 + ci];
    }
    if (i < DD) { g_sum[i] = 0.f; g_sumsq[i] = 0.f; }
    if (i < 64) g_scanstate[i] = 0ull;
    if (i < E) atomicAdd(&g_deg[ei[E + i]], 1);
}

// ---------------- launch 2: decoupled-lookback scan -> g_off/g_woff ----------
// 49 blocks (all resident), 1024 elements/block. Also zeroes g_deg for the
// NEXT kernel_launch invocation (stream-ordered).
#define FLAG_AGG 1ull
#define FLAG_PRE 2ull
__global__ __launch_bounds__(256) void k_scan(int n) {
    __shared__ int wtot[8], wpre[8], sExcl;
    int b = blockIdx.x, tid = threadIdx.x;
    int lane = tid & 31, w = tid >> 5;

    int4 d = ((const int4*)g_deg)[b * 256 + tid];
    ((int4*)g_deg)[b * 256 + tid] = make_int4(0, 0, 0, 0);   // reset for next call

    int s0 = d.x, s01 = s0 + d.y, s012 = s01 + d.z;
    int tsum = s012 + d.w;
    int inc = tsum;
    #pragma unroll
    for (int o = 1; o < 32; o <<= 1) {
        int u = __shfl_up_sync(FULLMASK, inc, o);
        if (lane >= o) inc += u;
    }
    if (lane == 31) wtot[w] = inc;
    __syncthreads();
    if (w == 0 && lane < 8) {
        int v = wtot[lane];
        int s = v;
        #pragma unroll
        for (int o = 1; o < 8; o <<= 1) {
            int u = __shfl_up_sync(0xffu, s, o);
            if (lane >= o) s += u;
        }
        wpre[lane] = s - v;
    }
    __syncthreads();
    int blockTotal = wpre[7] + wtot[7];

    if (tid == 0) {
        if (b == 0) {
            atomicExch(&g_scanstate[0], (FLAG_PRE << 32) | (unsigned)blockTotal);
            sExcl = 0;
        } else {
            atomicExch(&g_scanstate[b], (FLAG_AGG << 32) | (unsigned)blockTotal);
            int excl = 0;
            int look = b - 1;
            while (true) {
                ull word = atomicAdd(&g_scanstate[look], 0ull);
                ull flag = word >> 32;
                if (flag == 0) continue;               // predecessor not ready
                excl += (int)(word & 0xffffffffull);
                if (flag == FLAG_PRE) break;
                look--;
            }
            atomicExch(&g_scanstate[b],
                       (FLAG_PRE << 32) | (unsigned)(excl + blockTotal));
            sExcl = excl;
        }
    }
    __syncthreads();

    int excl = inc - tsum + wpre[w] + sExcl;
    int idx = b * 1024 + tid * 4;
    if (idx     <= n) { g_off[idx]     = excl;        g_woff[idx]     = excl; }
    if (idx + 1 <= n) { g_off[idx + 1] = excl + s0;   g_woff[idx + 1] = excl + s0; }
    if (idx + 2 <= n) { g_off[idx + 2] = excl + s01;  g_woff[idx + 2] = excl + s01; }
    if (idx + 3 <= n) { g_off[idx + 3] = excl + s012; g_woff[idx + 3] = excl + s012; }
}

// ---------------- launch 3: node transform + scatter (merged) ----------------
__global__ __launch_bounds__(256, 2) void k_nodescatter(
    const int* __restrict__ x, const float* __restrict__ emb,
    const float* __restrict__ bl, const float* __restrict__ br,
    const int* __restrict__ ei, int n, int E, int nodeBlocks)
{
    __shared__ float hs[2][32 * DD];   // 32 KB ping-pong
    if (blockIdx.x >= nodeBlocks) {
        // scatter path
        int e = (blockIdx.x - nodeBlocks) * 256 + threadIdx.x;
        if (e < E) {
            int dst = ei[E + e];
            int pos = atomicAdd(&g_woff[dst], 1);
            g_perm[pos] = e;
        }
        return;
    }

    int tid = threadIdx.x;
    int tc = tid & 31;
    int g  = tid >> 5;
    int mat = g & 1;
    int tr  = g >> 1;
    float4 bv = ((const float4*)(mat ? br : bl))[tc];
    float* gout = mat ? g_xr : g_xl;
    const float SQ = 11.313708498984761f;
    int ntiles = (n + 31) >> 5;

    int t = blockIdx.x;
    if (t >= ntiles) return;
    int cur = 0;

    {
        int base = t * 32;
        int nrows = min(32, n - base);
        for (int i = tid; i < 32 * 32; i += 256) {
            int r = i >> 5, c4 = i & 31;
            float4 v = make_float4(0.f, 0.f, 0.f, 0.f);
            if (r < nrows) {
                const float4* src = (const float4*)(emb + (size_t)x[base + r] * DD);
                v = src[c4];
                v.x *= SQ; v.y *= SQ; v.z *= SQ; v.w *= SQ;
            }
            ((float4*)hs[cur])[i] = v;
        }
    }
    __syncthreads();

    while (t < ntiles) {
        int tn = t + nodeBlocks;
        if (tn < ntiles) {
            int base = tn * 32;
            int nrows = min(32, n - base);
            for (int i = tid; i < 32 * 32; i += 256) {
                int r = i >> 5, c4 = i & 31;
                float4 v = make_float4(0.f, 0.f, 0.f, 0.f);
                if (r < nrows) {
                    const float4* src = (const float4*)(emb + (size_t)x[base + r] * DD);
                    v = src[c4];
                    v.x *= SQ; v.y *= SQ; v.z *= SQ; v.w *= SQ;
                }
                ((float4*)hs[cur ^ 1])[i] = v;
            }
        }

        ull acc[8][4];
        #pragma unroll
        for (int r = 0; r < 8; r++)
            #pragma unroll
            for (int c = 0; c < 4; c++) acc[r][c] = 0ull;

        const float* hbase = hs[cur] + tr * 8 * DD;
        const float* wbase = g_Wp + mat * 256 + tc * 4;
        #pragma unroll 2
        for (int kp = 0; kp < 64; kp++) {
            ulonglong2 L0 = *(const ulonglong2*)(wbase + kp * 512);
            ulonglong2 L1 = *(const ulonglong2*)(wbase + kp * 512 + 128);
            ull wv[4] = { L0.x, L0.y, L1.x, L1.y };
            #pragma unroll
            for (int r = 0; r < 8; r++) {
                ull hp = *(const ull*)(hbase + r * DD + 2 * kp);
                #pragma unroll
                for (int c = 0; c < 4; c++)
                    fma2(acc[r][c], hp, wv[c]);
            }
        }

        int base = t * 32;
        #pragma unroll
        for (int r = 0; r < 8; r++) {
            int row = base + tr * 8 + r;
            if (row < n) {
                F2U t0, t1, t2, t3;
                t0.u = acc[r][0]; t1.u = acc[r][1];
                t2.u = acc[r][2]; t3.u = acc[r][3];
                float4 o = make_float4(t0.f.x + t0.f.y + bv.x, t1.f.x + t1.f.y + bv.y,
                                       t2.f.x + t2.f.y + bv.z, t3.f.x + t3.f.y + bv.w);
                *(float4*)(gout + (size_t)row * DD + tc * 4) = o;
            }
        }
        __syncthreads();
        cur ^= 1;
        t = tn;
    }
}

// ---------------- launch 4 (PROFILED): fused score+softmax+agg+BN stats ------
__device__ __forceinline__ void edge_compute(
    const float* eew, float4 xlv, float4 xrv, float4 a4,
    const ull (&wreg)[8][4], float4 &acc, float &ds)
{
    ull p0 = 0, p1 = 0, p2 = 0, p3 = 0;
    #pragma unroll
    for (int dp = 0; dp < 8; dp++) {
        ull a = *(const ull*)(eew + 2 * dp);   // smem broadcast
        fma2(p0, a, wreg[dp][0]);
        fma2(p1, a, wreg[dp][1]);
        fma2(p2, a, wreg[dp][2]);
        fma2(p3, a, wreg[dp][3]);
    }
    F2U u0, u1, u2, u3;
    u0.u = p0; u1.u = p1; u2.u = p2; u3.u = p3;
    float mx = xlv.x + xrv.x + u0.f.x + u0.f.y;
    float my = xlv.y + xrv.y + u1.f.x + u1.f.y;
    float mz = xlv.z + xrv.z + u2.f.x + u2.f.y;
    float mw = xlv.w + xrv.w + u3.f.x + u3.f.y;
    mx = mx > 0.f ? mx : 0.2f * mx;
    my = my > 0.f ? my : 0.2f * my;
    mz = mz > 0.f ? mz : 0.2f * mz;
    mw = mw > 0.f ? mw : 0.2f * mw;
    float s = mx * a4.x + my * a4.y + mz * a4.z + mw * a4.w;
    s += __shfl_xor_sync(FULLMASK, s, 1);
    s += __shfl_xor_sync(FULLMASK, s, 2);
    float w = __expf(s);
    ds += w;
    acc.x = fmaf(w, xlv.x, acc.x);
    acc.y = fmaf(w, xlv.y, acc.y);
    acc.z = fmaf(w, xlv.z, acc.z);
    acc.w = fmaf(w, xlv.w, acc.w);
}

#define EDGE_STAGE(Q)                                                          \
    {                                                                          \
        const float* ep = sew + j * EDIM;                                      \
        float4 xlv = Q;                                                        \
        if (j + 4 < m) {                                                       \
            int s4i = __shfl_sync(FULLMASK, sL, j + 4);                        \
            Q = *(const float4*)(g_xl + (size_t)s4i * DD + col);               \
        }                                                                      \
        edge_compute(ep, xlv, xrv, a4, wreg, acc, ds);                         \
        j++;                                                                   \
    }

__global__ __launch_bounds__(128, 4) void k_fused(
    const int* __restrict__ ei, const float* __restrict__ ew,
    const float* __restrict__ We, const float* __restrict__ att,
    const float* __restrict__ bias, float* __restrict__ out, int n)
{
    __shared__ float sew_all[4][32 * EDIM];   // 8 KB
    __shared__ float ssum[4][DD], ssq[4][DD]; // 4 KB
    int lane = threadIdx.x & 31;
    int wid  = threadIdx.x >> 5;
    float* sew = sew_all[wid];
    int gw = blockIdx.x * 4 + wid;
    int nw = gridDim.x * 4;
    int col = lane * 4;

    ull wreg[8][4];
    #pragma unroll
    for (int dp = 0; dp < 8; dp++) {
        #pragma unroll
        for (int c = 0; c < 4; c++) {
            F2U t;
            t.f.x = __ldg(We + (2 * dp)     * DD + col + c);
            t.f.y = __ldg(We + (2 * dp + 1) * DD + col + c);
            wreg[dp][c] = t.u;
        }
    }
    float4 a4 = ((const float4*)att)[lane];
    float4 b4 = ((const float4*)bias)[lane];
    float4 sacc = make_float4(0.f, 0.f, 0.f, 0.f);
    float4 qacc = make_float4(0.f, 0.f, 0.f, 0.f);

    for (int v = gw; v < n; v += nw) {
        int start = g_off[v];
        int end   = g_off[v + 1];
        float4 xrv = *(const float4*)(g_xr + (size_t)v * DD + col);
        float4 acc = make_float4(0.f, 0.f, 0.f, 0.f);
        float ds = 0.f;

        for (int c0 = start; c0 < end; c0 += 32) {
            int m = min(32, end - c0);
            int sL = 0;
            if (lane < m) {
                int eL = g_perm[c0 + lane];
                sL = __ldg(ei + eL);
                const float4* src = (const float4*)(ew + (size_t)eL * EDIM);
                float4* dst = (float4*)(sew + lane * EDIM);
                dst[0] = src[0]; dst[1] = src[1]; dst[2] = src[2]; dst[3] = src[3];
            }
            __syncwarp();

            int s0 = __shfl_sync(FULLMASK, sL, 0);
            int s1 = __shfl_sync(FULLMASK, sL, 1);
            int s2 = __shfl_sync(FULLMASK, sL, 2);
            int s3 = __shfl_sync(FULLMASK, sL, 3);
            float4 xq0 = *(const float4*)(g_xl + (size_t)s0 * DD + col);
            float4 xq1 = *(const float4*)(g_xl + (size_t)s1 * DD + col);
            float4 xq2 = *(const float4*)(g_xl + (size_t)s2 * DD + col);
            float4 xq3 = *(const float4*)(g_xl + (size_t)s3 * DD + col);

            int j = 0;
            while (j < m) {
                EDGE_STAGE(xq0)
                if (j >= m) break;
                EDGE_STAGE(xq1)
                if (j >= m) break;
                EDGE_STAGE(xq2)
                if (j >= m) break;
                EDGE_STAGE(xq3)
            }
            __syncwarp();
        }
        float invd = (end > start) ? 1.f / ds : 0.f;
        float4 o = make_float4(fmaf(acc.x, invd, b4.x), fmaf(acc.y, invd, b4.y),
                               fmaf(acc.z, invd, b4.z), fmaf(acc.w, invd, b4.w));
        *(float4*)(out + (size_t)v * DD + col) = o;
        sacc.x += o.x; sacc.y += o.y; sacc.z += o.z; sacc.w += o.w;
        qacc.x = fmaf(o.x, o.x, qacc.x);
        qacc.y = fmaf(o.y, o.y, qacc.y);
        qacc.z = fmaf(o.z, o.z, qacc.z);
        qacc.w = fmaf(o.w, o.w, qacc.w);
    }

    *(float4*)&ssum[wid][col] = sacc;
    *(float4*)&ssq[wid][col]  = qacc;
    __syncthreads();
    int ch = threadIdx.x;
    float s = ssum[0][ch] + ssum[1][ch] + ssum[2][ch] + ssum[3][ch];
    float q = ssq[0][ch]  + ssq[1][ch]  + ssq[2][ch]  + ssq[3][ch];
    atomicAdd(&g_sum[ch], s);
    atomicAdd(&g_sumsq[ch], q);
}

// ---------------- launch 5: BN finalize + apply ----------------
__global__ __launch_bounds__(256) void k_apply(
    const float* __restrict__ gamma, const float* __restrict__ beta,
    float* __restrict__ out, int n)
{
    __shared__ float ssc[DD], ssh[DD];
    int t = threadIdx.x;
    if (t < DD) {
        float invn = 1.f / (float)n;
        float mean = g_sum[t] * invn;
        float var  = g_sumsq[t] * invn - mean * mean;
        if (var < 0.f) var = 0.f;
        float inv = rsqrtf(var + 1e-5f);
        float sc = gamma[t] * inv;
        ssc[t] = sc;
        ssh[t] = beta[t] - mean * sc;
    }
    __syncthreads();
    int i = blockIdx.x * blockDim.x + t;
    int total = n * (DD / 4);
    if (i < total) {
        float4 v = ((float4*)out)[i];
        float4 sc = ((float4*)ssc)[i & 31];
        float4 sh = ((float4*)ssh)[i & 31];
        float yx = fmaf(v.x, sc.x, sh.x);
        float yy = fmaf(v.y, sc.y, sh.y);
        float yz = fmaf(v.z, sc.z, sh.z);
        float yw = fmaf(v.w, sc.w, sh.w);
        v.x = yx > 0.f ? yx : 0.01f * yx;
        v.y = yy > 0.f ? yy : 0.01f * yy;
        v.z = yz > 0.f ? yz : 0.01f * yz;
        v.w = yw > 0.f ? yw : 0.01f * yw;
        ((float4*)out)[i] = v;
    }
}

// ---------------- launch ----------------
extern "C" void kernel_launch(void* const* d_in, const int* in_sizes, int n_in,
                              void* d_out, int out_size)
{
    const int*   x     = (const int*)  d_in[0];
    const int*   ei    = (const int*)  d_in[1];
    const float* ew    = (const float*)d_in[2];
    const float* emb   = (const float*)d_in[3];
    const float* Wl    = (const float*)d_in[4];
    const float* bl    = (const float*)d_in[5];
    const float* Wr    = (const float*)d_in[6];
    const float* br    = (const float*)d_in[7];
    const float* att   = (const float*)d_in[8];
    const float* We    = (const float*)d_in[9];
    const float* bias  = (const float*)d_in[10];
    const float* gamma = (const float*)d_in[11];
    const float* beta  = (const float*)d_in[12];
    float* out = (float*)d_out;

    int n = in_sizes[0];
    int E = in_sizes[1] / 2;
    int nb = (n + 1023) / 1024;
    int eb = (E + 255) / 256;

    k_pre<<<eb, 256>>>(Wl, Wr, ei, E);                       // 1
    k_scan<<<nb, 256>>>(n);                                  // 2
    k_nodescatter<<<296 + eb, 256>>>(x, emb, bl, br, ei, n, E, 296);  // 3
    k_fused<<<592, 128>>>(ei, ew, We, att, bias, out, n);    // 4 -> ncu capture
    k_apply<<<(n * (DD / 4) + 255) / 256, 256>>>(gamma, beta, out, n);  // 5
}